// round 1
// baseline (speedup 1.0000x reference)
#include <cuda_runtime.h>
#include <cstdint>
#include <cstddef>

// Problem constants
#define CB 2
#define CT 2048
#define CC 1024
#define CH 16
#define CHD 64
#define MROWS (CB*CT)          // 4096

// ---------------------------------------------------------------------------
// Scratch (device globals — no allocation allowed)
// ---------------------------------------------------------------------------
__device__ float g_Wqkv[(size_t)CC * 3 * CC];          // [1024, 3072]
__device__ float g_qkv [(size_t)MROWS * 3 * CC];       // [4096, 3072]
__device__ float g_attn[(size_t)MROWS * CC];           // [4096, 1024]
__device__ float g_x1  [(size_t)MROWS * CC];
__device__ float g_xln1[(size_t)MROWS * CC];
__device__ float g_ffn [(size_t)MROWS * 4 * CC];       // [4096, 4096]
__device__ float g_x2  [(size_t)MROWS * CC];

// ---------------------------------------------------------------------------
// Repack per-head weights [H, C, HD] x3  ->  [C, 3C] combined GEMM B matrix
// ---------------------------------------------------------------------------
__global__ void repack_kernel(const float* __restrict__ Wq,
                              const float* __restrict__ Wk,
                              const float* __restrict__ Wv,
                              float* __restrict__ W) {
    int idx = blockIdx.x * 256 + threadIdx.x;   // over C*C = 1M
    int c = idx >> 10;
    int n = idx & 1023;
    int h = n >> 6;
    int d = n & 63;
    size_t src = ((size_t)h * CC + c) * CHD + d;
    size_t dst = (size_t)c * (3 * CC) + n;
    W[dst]            = Wq[src];
    W[dst + CC]       = Wk[src];
    W[dst + 2 * CC]   = Wv[src];
}

// ---------------------------------------------------------------------------
// SGEMM: C[M,N] = A[M,K] @ B[K,N] (+bias) (+residual) (+relu)
// 128x128 block tile, BK=16, 256 threads, 8x8 microtile, fp32
// Requires M%128==0, N%128==0, K%16==0 (all shapes here satisfy this).
// ---------------------------------------------------------------------------
__global__ __launch_bounds__(256) void sgemm_kernel(
    const float* __restrict__ A, const float* __restrict__ B,
    const float* __restrict__ bias, const float* __restrict__ res,
    float* __restrict__ C, int M, int N, int K, int relu)
{
    __shared__ float As[16][132];   // [k][m], padded
    __shared__ float Bs[16][128];   // [k][n]

    const int tid = threadIdx.x;
    const int m0 = blockIdx.y * 128;
    const int n0 = blockIdx.x * 128;
    const int ty = tid >> 4;        // 0..15
    const int tx = tid & 15;        // 0..15

    float acc[8][8];
#pragma unroll
    for (int i = 0; i < 8; i++)
#pragma unroll
        for (int j = 0; j < 8; j++) acc[i][j] = 0.f;

    for (int kt = 0; kt < K; kt += 16) {
#pragma unroll
        for (int l = 0; l < 2; l++) {
            int idx = tid + l * 256;            // 0..511
            // A tile: 128 rows x 16 cols = 512 float4
            int ar = idx >> 2;
            int ac = (idx & 3) * 4;
            float4 av = *(const float4*)(A + (size_t)(m0 + ar) * K + kt + ac);
            As[ac + 0][ar] = av.x;
            As[ac + 1][ar] = av.y;
            As[ac + 2][ar] = av.z;
            As[ac + 3][ar] = av.w;
            // B tile: 16 rows x 128 cols = 512 float4
            int br = idx >> 5;
            int bc = (idx & 31) * 4;
            *(float4*)&Bs[br][bc] =
                *(const float4*)(B + (size_t)(kt + br) * N + n0 + bc);
        }
        __syncthreads();

#pragma unroll
        for (int k = 0; k < 16; k++) {
            float a[8], b[8];
            *(float4*)&a[0] = *(float4*)&As[k][ty * 4];
            *(float4*)&a[4] = *(float4*)&As[k][64 + ty * 4];
            *(float4*)&b[0] = *(float4*)&Bs[k][tx * 4];
            *(float4*)&b[4] = *(float4*)&Bs[k][64 + tx * 4];
#pragma unroll
            for (int i = 0; i < 8; i++)
#pragma unroll
                for (int j = 0; j < 8; j++)
                    acc[i][j] += a[i] * b[j];
        }
        __syncthreads();
    }

    // Epilogue
#pragma unroll
    for (int i = 0; i < 8; i++) {
        int r = m0 + ((i < 4) ? (ty * 4 + i) : (64 + ty * 4 + i - 4));
#pragma unroll
        for (int jh = 0; jh < 2; jh++) {
            int cb = n0 + jh * 64 + tx * 4;
            float4 v;
            v.x = acc[i][jh * 4 + 0];
            v.y = acc[i][jh * 4 + 1];
            v.z = acc[i][jh * 4 + 2];
            v.w = acc[i][jh * 4 + 3];
            if (bias) {
                float4 bb = *(const float4*)(bias + cb);
                v.x += bb.x; v.y += bb.y; v.z += bb.z; v.w += bb.w;
            }
            if (res) {
                float4 rr = *(const float4*)(res + (size_t)r * N + cb);
                v.x += rr.x; v.y += rr.y; v.z += rr.z; v.w += rr.w;
            }
            if (relu) {
                v.x = fmaxf(v.x, 0.f); v.y = fmaxf(v.y, 0.f);
                v.z = fmaxf(v.z, 0.f); v.w = fmaxf(v.w, 0.f);
            }
            *(float4*)(C + (size_t)r * N + cb) = v;
        }
    }
}

// ---------------------------------------------------------------------------
// Flash attention (causal), fp32. One block = 128 query rows for one (b,h).
// qkv layout: [B*T, 3072]; q at col h*64+d, k at +1024, v at +2048.
// Output: [B*T, 1024] (cols h*64+d) => directly the concat-heads layout.
// ---------------------------------------------------------------------------
#define QT_S 132
#define KT_S 68
#define PT_S 132
#define FLASH_SMEM ((64*QT_S + 64*KT_S + 64*64 + 64*PT_S) * 4)

__global__ __launch_bounds__(256) void flash_kernel(
    const float* __restrict__ qkv, float* __restrict__ out)
{
    extern __shared__ float smf[];
    float* Qt = smf;                  // [d][r] 64 x 132
    float* Kt = Qt + 64 * QT_S;       // [d][c] 64 x 68
    float* Vs = Kt + 64 * KT_S;       // [c][d] 64 x 64
    float* Pt = Vs + 64 * 64;         // [c][r] 64 x 132

    const int tid = threadIdx.x;
    const int tx = tid & 15;
    const int ty = tid >> 4;
    const int q0 = blockIdx.x * 128;
    const int h = blockIdx.y;
    const int b = blockIdx.z;
    const float scale = 0.125f;      // 1/sqrt(64)
    const size_t rs = 3 * CC;        // 3072

    const float* qbase = qkv + ((size_t)b * CT + q0) * rs + h * 64;
    const float* kbase = qkv + (size_t)b * CT * rs + CC + h * 64;
    const float* vbase = kbase + CC;

    // Load Q tile (128 rows x 64 cols) transposed into Qt[d][r]
#pragma unroll
    for (int l = 0; l < 8; l++) {
        int idx = tid + l * 256;        // 0..2047 float4s
        int r = idx >> 4;
        int d4 = (idx & 15) * 4;
        float4 qv = *(const float4*)(qbase + (size_t)r * rs + d4);
        Qt[(d4 + 0) * QT_S + r] = qv.x;
        Qt[(d4 + 1) * QT_S + r] = qv.y;
        Qt[(d4 + 2) * QT_S + r] = qv.z;
        Qt[(d4 + 3) * QT_S + r] = qv.w;
    }

    float m[8], lsum[8];
    float o[8][4];
#pragma unroll
    for (int i = 0; i < 8; i++) {
        m[i] = -1e30f;
        lsum[i] = 0.f;
#pragma unroll
        for (int c = 0; c < 4; c++) o[i][c] = 0.f;
    }

    const int jmax = (q0 + 127) >> 6;
    for (int j = 0; j <= jmax; j++) {
        __syncthreads();   // previous tile's Pt/Vs reads complete + Qt ready (j==0)
        const float* kp = kbase + (size_t)(j * 64) * rs;
        const float* vp = vbase + (size_t)(j * 64) * rs;
#pragma unroll
        for (int l = 0; l < 4; l++) {
            int idx = tid + l * 256;    // 0..1023 float4s
            int r = idx >> 4;           // key row within tile
            int d4 = (idx & 15) * 4;
            float4 kv = *(const float4*)(kp + (size_t)r * rs + d4);
            Kt[(d4 + 0) * KT_S + r] = kv.x;
            Kt[(d4 + 1) * KT_S + r] = kv.y;
            Kt[(d4 + 2) * KT_S + r] = kv.z;
            Kt[(d4 + 3) * KT_S + r] = kv.w;
            float4 vv = *(const float4*)(vp + (size_t)r * rs + d4);
            *(float4*)&Vs[r * 64 + d4] = vv;
        }
        __syncthreads();

        // S = Q @ K^T : 8 rows x 4 cols per thread
        float s[8][4];
#pragma unroll
        for (int i = 0; i < 8; i++)
#pragma unroll
            for (int c = 0; c < 4; c++) s[i][c] = 0.f;

#pragma unroll 8
        for (int d = 0; d < 64; d++) {
            float4 kv = *(float4*)&Kt[d * KT_S + tx * 4];
            float4 qa = *(float4*)&Qt[d * QT_S + ty * 8];
            float4 qb = *(float4*)&Qt[d * QT_S + ty * 8 + 4];
            float qv[8] = {qa.x, qa.y, qa.z, qa.w, qb.x, qb.y, qb.z, qb.w};
            float kk[4] = {kv.x, kv.y, kv.z, kv.w};
#pragma unroll
            for (int i = 0; i < 8; i++)
#pragma unroll
                for (int c = 0; c < 4; c++)
                    s[i][c] += qv[i] * kk[c];
        }

        const bool domask = (j * 64 + 63 > q0);
#pragma unroll
        for (int i = 0; i < 8; i++) {
            int qrow = q0 + ty * 8 + i;
            float sv[4];
#pragma unroll
            for (int c = 0; c < 4; c++) {
                float v = s[i][c] * scale;
                if (domask && (j * 64 + tx * 4 + c > qrow)) v = -1e30f;
                sv[c] = v;
            }
            float mloc = fmaxf(fmaxf(sv[0], sv[1]), fmaxf(sv[2], sv[3]));
#pragma unroll
            for (int off = 8; off >= 1; off >>= 1)
                mloc = fmaxf(mloc, __shfl_xor_sync(0xffffffffu, mloc, off, 16));
            float mnew = fmaxf(m[i], mloc);
            float corr = __expf(m[i] - mnew);
            float p[4];
            float ls = 0.f;
#pragma unroll
            for (int c = 0; c < 4; c++) {
                p[c] = __expf(sv[c] - mnew);
                ls += p[c];
            }
#pragma unroll
            for (int off = 8; off >= 1; off >>= 1)
                ls += __shfl_xor_sync(0xffffffffu, ls, off, 16);
            lsum[i] = lsum[i] * corr + ls;
            m[i] = mnew;
#pragma unroll
            for (int c = 0; c < 4; c++) o[i][c] *= corr;
            int rr = ty * 8 + i;
#pragma unroll
            for (int c = 0; c < 4; c++)
                Pt[(tx * 4 + c) * PT_S + rr] = p[c];
        }
        __syncthreads();

        // O += P @ V
#pragma unroll 8
        for (int c = 0; c < 64; c++) {
            float4 vv = *(float4*)&Vs[c * 64 + tx * 4];
            float4 pa = *(float4*)&Pt[c * PT_S + ty * 8];
            float4 pb = *(float4*)&Pt[c * PT_S + ty * 8 + 4];
            float pv[8] = {pa.x, pa.y, pa.z, pa.w, pb.x, pb.y, pb.z, pb.w};
#pragma unroll
            for (int i = 0; i < 8; i++) {
                o[i][0] += pv[i] * vv.x;
                o[i][1] += pv[i] * vv.y;
                o[i][2] += pv[i] * vv.z;
                o[i][3] += pv[i] * vv.w;
            }
        }
    }

    // Normalize and write to [B*T, C] concat-heads layout
    float* ob = out + ((size_t)b * CT + q0) * CC + h * 64;
#pragma unroll
    for (int i = 0; i < 8; i++) {
        float inv = 1.0f / lsum[i];
        float4 v;
        v.x = o[i][0] * inv;
        v.y = o[i][1] * inv;
        v.z = o[i][2] * inv;
        v.w = o[i][3] * inv;
        *(float4*)(ob + (size_t)(ty * 8 + i) * CC + tx * 4) = v;
    }
}

// ---------------------------------------------------------------------------
// LayerNorm over last dim (C=1024). One block per row, 256 threads.
// ---------------------------------------------------------------------------
__global__ __launch_bounds__(256) void ln_kernel(
    const float* __restrict__ in, const float* __restrict__ g,
    const float* __restrict__ bb, float* __restrict__ out)
{
    const int row = blockIdx.x;
    const int tid = threadIdx.x;
    float4 v = *(const float4*)(in + (size_t)row * CC + tid * 4);
    float s = v.x + v.y + v.z + v.w;
    float q = v.x * v.x + v.y * v.y + v.z * v.z + v.w * v.w;
#pragma unroll
    for (int off = 16; off >= 1; off >>= 1) {
        s += __shfl_xor_sync(0xffffffffu, s, off);
        q += __shfl_xor_sync(0xffffffffu, q, off);
    }
    __shared__ float ss[8], sq[8];
    __shared__ float smu, srs;
    int w = tid >> 5;
    if ((tid & 31) == 0) { ss[w] = s; sq[w] = q; }
    __syncthreads();
    if (tid == 0) {
        float S = 0.f, Q = 0.f;
#pragma unroll
        for (int i = 0; i < 8; i++) { S += ss[i]; Q += sq[i]; }
        float mu = S * (1.0f / CC);
        float var = Q * (1.0f / CC) - mu * mu;
        smu = mu;
        srs = rsqrtf(var + 1e-5f);
    }
    __syncthreads();
    float mu = smu, r = srs;
    float4 gv = *(const float4*)(g + tid * 4);
    float4 bv = *(const float4*)(bb + tid * 4);
    float4 ov;
    ov.x = (v.x - mu) * r * gv.x + bv.x;
    ov.y = (v.y - mu) * r * gv.y + bv.y;
    ov.z = (v.z - mu) * r * gv.z + bv.z;
    ov.w = (v.w - mu) * r * gv.w + bv.w;
    *(float4*)(out + (size_t)row * CC + tid * 4) = ov;
}

// ---------------------------------------------------------------------------
// Launch
// ---------------------------------------------------------------------------
extern "C" void kernel_launch(void* const* d_in, const int* in_sizes, int n_in,
                              void* d_out, int out_size)
{
    const float* x   = (const float*)d_in[0];
    const float* Wq  = (const float*)d_in[1];
    const float* Wk  = (const float*)d_in[2];
    const float* Wv  = (const float*)d_in[3];
    const float* Wp  = (const float*)d_in[4];
    const float* bp  = (const float*)d_in[5];
    const float* W1  = (const float*)d_in[6];
    const float* b1  = (const float*)d_in[7];
    const float* W2  = (const float*)d_in[8];
    const float* b2  = (const float*)d_in[9];
    const float* g1  = (const float*)d_in[10];
    const float* be1 = (const float*)d_in[11];
    const float* g2  = (const float*)d_in[12];
    const float* be2 = (const float*)d_in[13];

    float *Wqkv, *qkvp, *attn, *x1, *xln1, *ffn, *x2;
    cudaGetSymbolAddress((void**)&Wqkv, g_Wqkv);
    cudaGetSymbolAddress((void**)&qkvp, g_qkv);
    cudaGetSymbolAddress((void**)&attn, g_attn);
    cudaGetSymbolAddress((void**)&x1,   g_x1);
    cudaGetSymbolAddress((void**)&xln1, g_xln1);
    cudaGetSymbolAddress((void**)&ffn,  g_ffn);
    cudaGetSymbolAddress((void**)&x2,   g_x2);

    cudaFuncSetAttribute(flash_kernel,
                         cudaFuncAttributeMaxDynamicSharedMemorySize,
                         FLASH_SMEM);

    // 1) repack combined QKV weight
    repack_kernel<<<4096, 256>>>(Wq, Wk, Wv, Wqkv);

    // 2) QKV = X @ Wqkv    [4096, 3072]
    sgemm_kernel<<<dim3(3 * CC / 128, MROWS / 128), 256>>>(
        x, Wqkv, nullptr, nullptr, qkvp, MROWS, 3 * CC, CC, 0);

    // 3) flash attention -> attn [4096, 1024]
    flash_kernel<<<dim3(CT / 128, CH, CB), 256, FLASH_SMEM>>>(qkvp, attn);

    // 4) x1 = attn @ Wp + bp + x
    sgemm_kernel<<<dim3(CC / 128, MROWS / 128), 256>>>(
        attn, Wp, bp, x, x1, MROWS, CC, CC, 0);

    // 5) xln1 = LN(x1)
    ln_kernel<<<MROWS, 256>>>(x1, g1, be1, xln1);

    // 6) ffn = relu(xln1 @ W1 + b1)   [4096, 4096]
    sgemm_kernel<<<dim3(4 * CC / 128, MROWS / 128), 256>>>(
        xln1, W1, b1, nullptr, ffn, MROWS, 4 * CC, CC, 1);

    // 7) x2 = ffn @ W2 + b2 + xln1
    sgemm_kernel<<<dim3(CC / 128, MROWS / 128), 256>>>(
        ffn, W2, b2, xln1, x2, MROWS, CC, 4 * CC, 0);

    // 8) out = LN(x2)
    ln_kernel<<<MROWS, 256>>>(x2, g2, be2, (float*)d_out);
}

// round 4
// speedup vs baseline: 2.1082x; 2.1082x over previous
#include <cuda_runtime.h>
#include <cstdint>
#include <cstddef>

// Problem constants
#define CB 2
#define CT 2048
#define CC 1024
#define CH 16
#define CHD 64
#define MROWS (CB*CT)          // 4096

// ---------------------------------------------------------------------------
// Helpers
// ---------------------------------------------------------------------------
__device__ __forceinline__ uint32_t smem_u32(const void* p) {
    uint32_t a;
    asm("{ .reg .u64 t; cvta.to.shared.u64 t, %1; cvt.u32.u64 %0, t; }"
        : "=r"(a) : "l"(p));
    return a;
}

__device__ __forceinline__ float rna_tf32(float x) {
    uint32_t r;
    asm("cvt.rna.tf32.f32 %0, %1;" : "=r"(r) : "f"(x));
    return __uint_as_float(r);
}

#define CP16(dst, src) \
    asm volatile("cp.async.cg.shared.global [%0], [%1], 16;" \
        :: "r"((uint32_t)(dst)), "l"(__cvta_generic_to_global((const void*)(src))))
#define CP_COMMIT() asm volatile("cp.async.commit_group;")
#define CP_WAIT(n)  asm volatile("cp.async.wait_group %0;" :: "n"(n) : "memory")

#define LDMX4(r0, r1, r2, r3, addr) \
    asm volatile("ldmatrix.sync.aligned.m8n8.x4.shared.b16 {%0,%1,%2,%3}, [%4];" \
        : "=r"(r0), "=r"(r1), "=r"(r2), "=r"(r3) : "r"(addr))

#define MMA_TF32(c, a, b0_, b1_) \
    asm volatile("mma.sync.aligned.m16n8k8.row.col.f32.tf32.tf32.f32 " \
        "{%0,%1,%2,%3}, {%4,%5,%6,%7}, {%8,%9}, {%0,%1,%2,%3};" \
        : "+f"((c)[0]), "+f"((c)[1]), "+f"((c)[2]), "+f"((c)[3]) \
        : "r"((a)[0]), "r"((a)[1]), "r"((a)[2]), "r"((a)[3]), \
          "r"(b0_), "r"(b1_))

// ---------------------------------------------------------------------------
// Scratch (device globals — no allocation allowed)
// ---------------------------------------------------------------------------
__device__ float g_WqkvT[(size_t)3 * CC * CC];          // [3072, 1024]
__device__ float g_WpT  [(size_t)CC * CC];
__device__ float g_W1T  [(size_t)4 * CC * CC];
__device__ float g_W2T  [(size_t)CC * 4 * CC];
__device__ float g_xr   [(size_t)MROWS * CC];           // x rounded to tf32
__device__ float g_qkv  [(size_t)MROWS * 3 * CC];
__device__ float g_attn [(size_t)MROWS * CC];
__device__ float g_x1   [(size_t)MROWS * CC];
__device__ float g_xln1 [(size_t)MROWS * CC];
__device__ float g_ffn  [(size_t)MROWS * 4 * CC];
__device__ float g_x2   [(size_t)MROWS * CC];

// ---------------------------------------------------------------------------
// repack+transpose QKV weights: [H, C, HD] x3 -> [3C, C] (rows=N, cols=K), rna
// ---------------------------------------------------------------------------
__global__ void repackT_kernel(const float* __restrict__ Wq,
                               const float* __restrict__ Wk,
                               const float* __restrict__ Wv,
                               float* __restrict__ Wt) {
    int idx = blockIdx.x * 256 + threadIdx.x;   // over 3C*C
    int c = idx & 1023;
    int n = idx >> 10;
    int sel = n >> 10;
    int hn = n & 1023;
    int h = hn >> 6;
    int d = hn & 63;
    const float* W = (sel == 0) ? Wq : (sel == 1) ? Wk : Wv;
    Wt[(size_t)n * CC + c] = rna_tf32(W[((size_t)h * CC + c) * CHD + d]);
}

// ---------------------------------------------------------------------------
// Tiled transpose (+rna): in [K, N] -> out [N, K]
// ---------------------------------------------------------------------------
__global__ void transpose_kernel(const float* __restrict__ in,
                                 float* __restrict__ out, int K, int N) {
    __shared__ float t[32][33];
    int n0 = blockIdx.x * 32;
    int k0 = blockIdx.y * 32;
    int x = threadIdx.x, y = threadIdx.y;     // 32 x 8
#pragma unroll
    for (int i = 0; i < 32; i += 8)
        t[y + i][x] = in[(size_t)(k0 + y + i) * N + n0 + x];
    __syncthreads();
#pragma unroll
    for (int i = 0; i < 32; i += 8)
        out[(size_t)(n0 + y + i) * K + k0 + x] = rna_tf32(t[x][y + i]);
}

// ---------------------------------------------------------------------------
// Elementwise rna-round copy
// ---------------------------------------------------------------------------
__global__ void round_copy_kernel(const float* __restrict__ in,
                                  float* __restrict__ out) {
    size_t i = ((size_t)blockIdx.x * 256 + threadIdx.x) * 4;
    float4 v = *(const float4*)(in + i);
    v.x = rna_tf32(v.x); v.y = rna_tf32(v.y);
    v.z = rna_tf32(v.z); v.w = rna_tf32(v.w);
    *(float4*)(out + i) = v;
}

// ---------------------------------------------------------------------------
// TF32 mma.sync GEMM: C[M,N] = A[M,K] @ Bt[N,K]^T (+bias)(+res)(relu)(rnd)
// 128x128 CTA, BK=32, 128 threads (4 warps, 2x2, 64x64 warp tile),
// double-buffered cp.async, swizzled ldmatrix fragments.
// A and Bt entries must already be tf32-rounded values.
// ---------------------------------------------------------------------------
#define GEMM_SMEM (4 * 16384)      // 2 stages x (A 16K + B 16K)

__device__ __forceinline__ void g_load_tile(const float* __restrict__ A,
                                            const float* __restrict__ Bt,
                                            int K, int m0, int n0, int kt,
                                            uint32_t aBase, uint32_t bBase,
                                            int tid) {
#pragma unroll
    for (int l = 0; l < 8; l++) {
        int idx = tid + (l << 7);            // 0..1023
        int r = idx >> 3;                    // row 0..127
        int c = idx & 7;                     // 16B chunk 0..7
        uint32_t dst = (uint32_t)((r << 7) + ((c ^ (r & 7)) << 4));
        CP16(aBase + dst, A + (size_t)(m0 + r) * K + kt + (c << 2));
        CP16(bBase + dst, Bt + (size_t)(n0 + r) * K + kt + (c << 2));
    }
}

__global__ __launch_bounds__(128) void tc_gemm_kernel(
    const float* __restrict__ A, const float* __restrict__ Bt,
    const float* __restrict__ bias, const float* __restrict__ res,
    float* __restrict__ C, int M, int N, int K, int relu, int rnd)
{
    extern __shared__ __align__(1024) char smem[];
    const uint32_t sb = smem_u32(smem);
    const int tid = threadIdx.x;
    const int lid = tid & 31;
    const int wid = tid >> 5;
    const int wm = wid >> 1;           // 0..1
    const int wn = wid & 1;            // 0..1
    const int q  = lid >> 3;           // quad 0..3
    const int l7 = lid & 7;
    const int m0 = blockIdx.y * 128;
    const int n0 = blockIdx.x * 128;

    // stage s: A at sb + s*32768, B at sb + s*32768 + 16384
    float acc[4][8][4];
#pragma unroll
    for (int i = 0; i < 4; i++)
#pragma unroll
        for (int j = 0; j < 8; j++)
#pragma unroll
            for (int k = 0; k < 4; k++) acc[i][j][k] = 0.f;

    const int NK = K >> 5;
    g_load_tile(A, Bt, K, m0, n0, 0, sb, sb + 16384, tid);
    CP_COMMIT();

    for (int ks = 0; ks < NK; ks++) {
        if (ks + 1 < NK) {
            uint32_t st = sb + (uint32_t)((ks + 1) & 1) * 32768u;
            g_load_tile(A, Bt, K, m0, n0, (ks + 1) << 5, st, st + 16384, tid);
            CP_COMMIT();
            CP_WAIT(1);
        } else {
            CP_WAIT(0);
        }
        __syncthreads();

        const uint32_t aB = sb + (uint32_t)(ks & 1) * 32768u;
        const uint32_t bB = aB + 16384u;

#pragma unroll
        for (int kk = 0; kk < 4; kk++) {           // k8-substeps; chunk pair base kk*2
            uint32_t a[4][4], b[4][4];
#pragma unroll
            for (int mt = 0; mt < 4; mt++) {
                int row = wm * 64 + mt * 16 + (q & 1) * 8 + l7;
                int ch = kk * 2 + (q >> 1);
                uint32_t addr = aB + (uint32_t)((row << 7) + ((ch ^ (row & 7)) << 4));
                LDMX4(a[mt][0], a[mt][1], a[mt][2], a[mt][3], addr);
            }
#pragma unroll
            for (int np = 0; np < 4; np++) {       // n-tile pairs
                int row = wn * 64 + np * 16 + (q >> 1) * 8 + l7;
                int ch = kk * 2 + (q & 1);
                uint32_t addr = bB + (uint32_t)((row << 7) + ((ch ^ (row & 7)) << 4));
                LDMX4(b[np][0], b[np][1], b[np][2], b[np][3], addr);
            }
#pragma unroll
            for (int mt = 0; mt < 4; mt++)
#pragma unroll
                for (int nt = 0; nt < 8; nt++)
                    MMA_TF32(acc[mt][nt], a[mt],
                             b[nt >> 1][(nt & 1) * 2],
                             b[nt >> 1][(nt & 1) * 2 + 1]);
        }
        __syncthreads();
    }

    // epilogue
    const int gid = lid >> 2;          // 0..7
    const int tig = lid & 3;           // 0..3
#pragma unroll
    for (int mt = 0; mt < 4; mt++) {
        int r0 = m0 + wm * 64 + mt * 16 + gid;
        int r1 = r0 + 8;
        float* c0row = C + (size_t)r0 * N;
        float* c1row = C + (size_t)r1 * N;
        const float* res0 = res ? res + (size_t)r0 * N : nullptr;
        const float* res1 = res ? res + (size_t)r1 * N : nullptr;
#pragma unroll
        for (int nt = 0; nt < 8; nt++) {
            int col = n0 + wn * 64 + nt * 8 + tig * 2;
            float2 v0 = make_float2(acc[mt][nt][0], acc[mt][nt][1]);
            float2 v1 = make_float2(acc[mt][nt][2], acc[mt][nt][3]);
            if (bias) {
                float2 bb = *(const float2*)(bias + col);
                v0.x += bb.x; v0.y += bb.y;
                v1.x += bb.x; v1.y += bb.y;
            }
            if (res) {
                float2 ra = *(const float2*)(res0 + col);
                float2 rb = *(const float2*)(res1 + col);
                v0.x += ra.x; v0.y += ra.y;
                v1.x += rb.x; v1.y += rb.y;
            }
            if (relu) {
                v0.x = fmaxf(v0.x, 0.f); v0.y = fmaxf(v0.y, 0.f);
                v1.x = fmaxf(v1.x, 0.f); v1.y = fmaxf(v1.y, 0.f);
            }
            if (rnd) {
                v0.x = rna_tf32(v0.x); v0.y = rna_tf32(v0.y);
                v1.x = rna_tf32(v1.x); v1.y = rna_tf32(v1.y);
            }
            *(float2*)(c0row + col) = v0;
            *(float2*)(c1row + col) = v1;
        }
    }
}

// ---------------------------------------------------------------------------
// Flash attention (causal), fp32. One block = 128 query rows for one (b,h).
// Output rounded to tf32 (feeds the projection GEMM).
// ---------------------------------------------------------------------------
#define QT_S 132
#define KT_S 68
#define PT_S 132
#define FLASH_SMEM ((64*QT_S + 64*KT_S + 64*64 + 64*PT_S) * 4)

__global__ __launch_bounds__(256) void flash_kernel(
    const float* __restrict__ qkv, float* __restrict__ out)
{
    extern __shared__ float smf[];
    float* Qt = smf;
    float* Kt = Qt + 64 * QT_S;
    float* Vs = Kt + 64 * KT_S;
    float* Pt = Vs + 64 * 64;

    const int tid = threadIdx.x;
    const int tx = tid & 15;
    const int ty = tid >> 4;
    const int q0 = blockIdx.x * 128;
    const int h = blockIdx.y;
    const int b = blockIdx.z;
    const float scale = 0.125f;
    const size_t rs = 3 * CC;

    const float* qbase = qkv + ((size_t)b * CT + q0) * rs + h * 64;
    const float* kbase = qkv + (size_t)b * CT * rs + CC + h * 64;
    const float* vbase = kbase + CC;

#pragma unroll
    for (int l = 0; l < 8; l++) {
        int idx = tid + l * 256;
        int r = idx >> 4;
        int d4 = (idx & 15) * 4;
        float4 qv = *(const float4*)(qbase + (size_t)r * rs + d4);
        Qt[(d4 + 0) * QT_S + r] = qv.x;
        Qt[(d4 + 1) * QT_S + r] = qv.y;
        Qt[(d4 + 2) * QT_S + r] = qv.z;
        Qt[(d4 + 3) * QT_S + r] = qv.w;
    }

    float m[8], lsum[8];
    float o[8][4];
#pragma unroll
    for (int i = 0; i < 8; i++) {
        m[i] = -1e30f; lsum[i] = 0.f;
#pragma unroll
        for (int c = 0; c < 4; c++) o[i][c] = 0.f;
    }

    const int jmax = (q0 + 127) >> 6;
    for (int j = 0; j <= jmax; j++) {
        __syncthreads();
        const float* kp = kbase + (size_t)(j * 64) * rs;
        const float* vp = vbase + (size_t)(j * 64) * rs;
#pragma unroll
        for (int l = 0; l < 4; l++) {
            int idx = tid + l * 256;
            int r = idx >> 4;
            int d4 = (idx & 15) * 4;
            float4 kv = *(const float4*)(kp + (size_t)r * rs + d4);
            Kt[(d4 + 0) * KT_S + r] = kv.x;
            Kt[(d4 + 1) * KT_S + r] = kv.y;
            Kt[(d4 + 2) * KT_S + r] = kv.z;
            Kt[(d4 + 3) * KT_S + r] = kv.w;
            float4 vv = *(const float4*)(vp + (size_t)r * rs + d4);
            *(float4*)&Vs[r * 64 + d4] = vv;
        }
        __syncthreads();

        float s[8][4];
#pragma unroll
        for (int i = 0; i < 8; i++)
#pragma unroll
            for (int c = 0; c < 4; c++) s[i][c] = 0.f;

#pragma unroll 8
        for (int d = 0; d < 64; d++) {
            float4 kv = *(float4*)&Kt[d * KT_S + tx * 4];
            float4 qa = *(float4*)&Qt[d * QT_S + ty * 8];
            float4 qb = *(float4*)&Qt[d * QT_S + ty * 8 + 4];
            float qv[8] = {qa.x, qa.y, qa.z, qa.w, qb.x, qb.y, qb.z, qb.w};
            float kk[4] = {kv.x, kv.y, kv.z, kv.w};
#pragma unroll
            for (int i = 0; i < 8; i++)
#pragma unroll
                for (int c = 0; c < 4; c++)
                    s[i][c] += qv[i] * kk[c];
        }

        const bool domask = (j * 64 + 63 > q0);
#pragma unroll
        for (int i = 0; i < 8; i++) {
            int qrow = q0 + ty * 8 + i;
            float sv[4];
#pragma unroll
            for (int c = 0; c < 4; c++) {
                float v = s[i][c] * scale;
                if (domask && (j * 64 + tx * 4 + c > qrow)) v = -1e30f;
                sv[c] = v;
            }
            float mloc = fmaxf(fmaxf(sv[0], sv[1]), fmaxf(sv[2], sv[3]));
#pragma unroll
            for (int off = 8; off >= 1; off >>= 1)
                mloc = fmaxf(mloc, __shfl_xor_sync(0xffffffffu, mloc, off, 16));
            float mnew = fmaxf(m[i], mloc);
            float corr = __expf(m[i] - mnew);
            float p[4];
            float ls = 0.f;
#pragma unroll
            for (int c = 0; c < 4; c++) {
                p[c] = __expf(sv[c] - mnew);
                ls += p[c];
            }
#pragma unroll
            for (int off = 8; off >= 1; off >>= 1)
                ls += __shfl_xor_sync(0xffffffffu, ls, off, 16);
            lsum[i] = lsum[i] * corr + ls;
            m[i] = mnew;
#pragma unroll
            for (int c = 0; c < 4; c++) o[i][c] *= corr;
            int rr = ty * 8 + i;
#pragma unroll
            for (int c = 0; c < 4; c++)
                Pt[(tx * 4 + c) * PT_S + rr] = p[c];
        }
        __syncthreads();

#pragma unroll 8
        for (int c = 0; c < 64; c++) {
            float4 vv = *(float4*)&Vs[c * 64 + tx * 4];
            float4 pa = *(float4*)&Pt[c * PT_S + ty * 8];
            float4 pb = *(float4*)&Pt[c * PT_S + ty * 8 + 4];
            float pv[8] = {pa.x, pa.y, pa.z, pa.w, pb.x, pb.y, pb.z, pb.w};
#pragma unroll
            for (int i = 0; i < 8; i++) {
                o[i][0] += pv[i] * vv.x;
                o[i][1] += pv[i] * vv.y;
                o[i][2] += pv[i] * vv.z;
                o[i][3] += pv[i] * vv.w;
            }
        }
    }

    float* ob = out + ((size_t)b * CT + q0) * CC + h * 64;
#pragma unroll
    for (int i = 0; i < 8; i++) {
        float inv = 1.0f / lsum[i];
        float4 v;
        v.x = rna_tf32(o[i][0] * inv);
        v.y = rna_tf32(o[i][1] * inv);
        v.z = rna_tf32(o[i][2] * inv);
        v.w = rna_tf32(o[i][3] * inv);
        *(float4*)(ob + (size_t)(ty * 8 + i) * CC + tx * 4) = v;
    }
}

// ---------------------------------------------------------------------------
// LayerNorm over last dim (C=1024). rnd=1 rounds output to tf32.
// ---------------------------------------------------------------------------
__global__ __launch_bounds__(256) void ln_kernel(
    const float* __restrict__ in, const float* __restrict__ g,
    const float* __restrict__ bb, float* __restrict__ out, int rnd)
{
    const int row = blockIdx.x;
    const int tid = threadIdx.x;
    float4 v = *(const float4*)(in + (size_t)row * CC + tid * 4);
    float s = v.x + v.y + v.z + v.w;
    float q = v.x * v.x + v.y * v.y + v.z * v.z + v.w * v.w;
#pragma unroll
    for (int off = 16; off >= 1; off >>= 1) {
        s += __shfl_xor_sync(0xffffffffu, s, off);
        q += __shfl_xor_sync(0xffffffffu, q, off);
    }
    __shared__ float ss[8], sq[8];
    __shared__ float smu, srs;
    int w = tid >> 5;
    if ((tid & 31) == 0) { ss[w] = s; sq[w] = q; }
    __syncthreads();
    if (tid == 0) {
        float S = 0.f, Q = 0.f;
#pragma unroll
        for (int i = 0; i < 8; i++) { S += ss[i]; Q += sq[i]; }
        float mu = S * (1.0f / CC);
        float var = Q * (1.0f / CC) - mu * mu;
        smu = mu;
        srs = rsqrtf(var + 1e-5f);
    }
    __syncthreads();
    float mu = smu, r = srs;
    float4 gv = *(const float4*)(g + tid * 4);
    float4 bv = *(const float4*)(bb + tid * 4);
    float4 ov;
    ov.x = (v.x - mu) * r * gv.x + bv.x;
    ov.y = (v.y - mu) * r * gv.y + bv.y;
    ov.z = (v.z - mu) * r * gv.z + bv.z;
    ov.w = (v.w - mu) * r * gv.w + bv.w;
    if (rnd) {
        ov.x = rna_tf32(ov.x); ov.y = rna_tf32(ov.y);
        ov.z = rna_tf32(ov.z); ov.w = rna_tf32(ov.w);
    }
    *(float4*)(out + (size_t)row * CC + tid * 4) = ov;
}

// ---------------------------------------------------------------------------
// Launch
// ---------------------------------------------------------------------------
extern "C" void kernel_launch(void* const* d_in, const int* in_sizes, int n_in,
                              void* d_out, int out_size)
{
    const float* x   = (const float*)d_in[0];
    const float* Wq  = (const float*)d_in[1];
    const float* Wk  = (const float*)d_in[2];
    const float* Wv  = (const float*)d_in[3];
    const float* Wp  = (const float*)d_in[4];
    const float* bp  = (const float*)d_in[5];
    const float* W1  = (const float*)d_in[6];
    const float* b1  = (const float*)d_in[7];
    const float* W2  = (const float*)d_in[8];
    const float* b2  = (const float*)d_in[9];
    const float* g1  = (const float*)d_in[10];
    const float* be1 = (const float*)d_in[11];
    const float* g2  = (const float*)d_in[12];
    const float* be2 = (const float*)d_in[13];

    float *WqkvT, *WpT, *W1T, *W2T, *xr, *qkvp, *attn, *x1, *xln1, *ffn, *x2;
    cudaGetSymbolAddress((void**)&WqkvT, g_WqkvT);
    cudaGetSymbolAddress((void**)&WpT,   g_WpT);
    cudaGetSymbolAddress((void**)&W1T,   g_W1T);
    cudaGetSymbolAddress((void**)&W2T,   g_W2T);
    cudaGetSymbolAddress((void**)&xr,    g_xr);
    cudaGetSymbolAddress((void**)&qkvp,  g_qkv);
    cudaGetSymbolAddress((void**)&attn,  g_attn);
    cudaGetSymbolAddress((void**)&x1,    g_x1);
    cudaGetSymbolAddress((void**)&xln1,  g_xln1);
    cudaGetSymbolAddress((void**)&ffn,   g_ffn);
    cudaGetSymbolAddress((void**)&x2,    g_x2);

    cudaFuncSetAttribute(flash_kernel,
                         cudaFuncAttributeMaxDynamicSharedMemorySize, FLASH_SMEM);
    cudaFuncSetAttribute(tc_gemm_kernel,
                         cudaFuncAttributeMaxDynamicSharedMemorySize, GEMM_SMEM);

    // 1) weight prep (tf32-rounded): repack+transpose QKV; transpose Wp/W1/W2
    repackT_kernel<<<3 * CC * CC / 256, 256>>>(Wq, Wk, Wv, WqkvT);
    transpose_kernel<<<dim3(CC / 32, CC / 32), dim3(32, 8)>>>(Wp, WpT, CC, CC);
    transpose_kernel<<<dim3(4 * CC / 32, CC / 32), dim3(32, 8)>>>(W1, W1T, CC, 4 * CC);
    transpose_kernel<<<dim3(CC / 32, 4 * CC / 32), dim3(32, 8)>>>(W2, W2T, 4 * CC, CC);
    round_copy_kernel<<<MROWS * CC / 1024, 256>>>(x, xr);

    // 2) QKV = Xr @ Wqkv  [4096, 3072]
    tc_gemm_kernel<<<dim3(3 * CC / 128, MROWS / 128), 128, GEMM_SMEM>>>(
        xr, WqkvT, nullptr, nullptr, qkvp, MROWS, 3 * CC, CC, 0, 0);

    // 3) flash attention -> attn [4096, 1024] (tf32-rounded output)
    flash_kernel<<<dim3(CT / 128, CH, CB), 256, FLASH_SMEM>>>(qkvp, attn);

    // 4) x1 = attn @ Wp + bp + x
    tc_gemm_kernel<<<dim3(CC / 128, MROWS / 128), 128, GEMM_SMEM>>>(
        attn, WpT, bp, x, x1, MROWS, CC, CC, 0, 0);

    // 5) xln1 = LN(x1), rounded (feeds FFN1 and residual)
    ln_kernel<<<MROWS, 256>>>(x1, g1, be1, xln1, 1);

    // 6) ffn = relu(xln1 @ W1 + b1), rounded (feeds FFN2)
    tc_gemm_kernel<<<dim3(4 * CC / 128, MROWS / 128), 128, GEMM_SMEM>>>(
        xln1, W1T, b1, nullptr, ffn, MROWS, 4 * CC, CC, 1, 1);

    // 7) x2 = ffn @ W2 + b2 + xln1
    tc_gemm_kernel<<<dim3(CC / 128, MROWS / 128), 128, GEMM_SMEM>>>(
        ffn, W2T, b2, xln1, x2, MROWS, CC, 4 * CC, 0, 0);

    // 8) out = LN(x2), unrounded
    ln_kernel<<<MROWS, 256>>>(x2, g2, be2, (float*)d_out, 0);
}

// round 5
// speedup vs baseline: 2.2203x; 1.0532x over previous
#include <cuda_runtime.h>
#include <cstdint>
#include <cstddef>

// Problem constants
#define CB 2
#define CT 2048
#define CC 1024
#define CH 16
#define CHD 64
#define MROWS (CB*CT)          // 4096

// ---------------------------------------------------------------------------
// Helpers
// ---------------------------------------------------------------------------
__device__ __forceinline__ uint32_t smem_u32(const void* p) {
    uint32_t a;
    asm("{ .reg .u64 t; cvta.to.shared.u64 t, %1; cvt.u32.u64 %0, t; }"
        : "=r"(a) : "l"(p));
    return a;
}

__device__ __forceinline__ float rna_tf32(float x) {
    uint32_t r;
    asm("cvt.rna.tf32.f32 %0, %1;" : "=r"(r) : "f"(x));
    return __uint_as_float(r);
}

#define CP16(dst, src) \
    asm volatile("cp.async.cg.shared.global [%0], [%1], 16;" \
        :: "r"((uint32_t)(dst)), "l"(__cvta_generic_to_global((const void*)(src))))
#define CP_COMMIT() asm volatile("cp.async.commit_group;")
#define CP_WAIT1()  asm volatile("cp.async.wait_group 1;" ::: "memory")
#define CP_WAIT0()  asm volatile("cp.async.wait_group 0;" ::: "memory")

#define LDMX4(r0, r1, r2, r3, addr) \
    asm volatile("ldmatrix.sync.aligned.m8n8.x4.shared.b16 {%0,%1,%2,%3}, [%4];" \
        : "=r"(r0), "=r"(r1), "=r"(r2), "=r"(r3) : "r"(addr))

#define MMA_TF32(c, a, b0_, b1_) \
    asm volatile("mma.sync.aligned.m16n8k8.row.col.f32.tf32.tf32.f32 " \
        "{%0,%1,%2,%3}, {%4,%5,%6,%7}, {%8,%9}, {%0,%1,%2,%3};" \
        : "+f"((c)[0]), "+f"((c)[1]), "+f"((c)[2]), "+f"((c)[3]) \
        : "r"((a)[0]), "r"((a)[1]), "r"((a)[2]), "r"((a)[3]), \
          "r"(b0_), "r"(b1_))

// ---------------------------------------------------------------------------
// Scratch (device globals — no allocation allowed)
// ---------------------------------------------------------------------------
__device__ float g_WqkvT[(size_t)3 * CC * CC];          // [3072, 1024]
__device__ float g_WpT  [(size_t)CC * CC];
__device__ float g_W1T  [(size_t)4 * CC * CC];
__device__ float g_W2T  [(size_t)CC * 4 * CC];
__device__ float g_xr   [(size_t)MROWS * CC];           // x rounded to tf32
__device__ float g_qkv  [(size_t)MROWS * 3 * CC];
__device__ float g_attn [(size_t)MROWS * CC];
__device__ float g_x1   [(size_t)MROWS * CC];
__device__ float g_xln1 [(size_t)MROWS * CC];
__device__ float g_ffn  [(size_t)MROWS * 4 * CC];
__device__ float g_x2   [(size_t)MROWS * CC];

// ---------------------------------------------------------------------------
// repack+transpose QKV weights: [H, C, HD] x3 -> [3C, C] (rows=N, cols=K), rna
// ---------------------------------------------------------------------------
__global__ void repackT_kernel(const float* __restrict__ Wq,
                               const float* __restrict__ Wk,
                               const float* __restrict__ Wv,
                               float* __restrict__ Wt) {
    int idx = blockIdx.x * 256 + threadIdx.x;   // over 3C*C
    int c = idx & 1023;
    int n = idx >> 10;
    int sel = n >> 10;
    int hn = n & 1023;
    int h = hn >> 6;
    int d = hn & 63;
    const float* W = (sel == 0) ? Wq : (sel == 1) ? Wk : Wv;
    Wt[(size_t)n * CC + c] = rna_tf32(W[((size_t)h * CC + c) * CHD + d]);
}

// ---------------------------------------------------------------------------
// Tiled transpose (+rna): in [K, N] -> out [N, K]
// ---------------------------------------------------------------------------
__global__ void transpose_kernel(const float* __restrict__ in,
                                 float* __restrict__ out, int K, int N) {
    __shared__ float t[32][33];
    int n0 = blockIdx.x * 32;
    int k0 = blockIdx.y * 32;
    int x = threadIdx.x, y = threadIdx.y;     // 32 x 8
#pragma unroll
    for (int i = 0; i < 32; i += 8)
        t[y + i][x] = in[(size_t)(k0 + y + i) * N + n0 + x];
    __syncthreads();
#pragma unroll
    for (int i = 0; i < 32; i += 8)
        out[(size_t)(n0 + y + i) * K + k0 + x] = rna_tf32(t[x][y + i]);
}

// ---------------------------------------------------------------------------
// Elementwise rna-round copy
// ---------------------------------------------------------------------------
__global__ void round_copy_kernel(const float* __restrict__ in,
                                  float* __restrict__ out) {
    size_t i = ((size_t)blockIdx.x * 256 + threadIdx.x) * 4;
    float4 v = *(const float4*)(in + i);
    v.x = rna_tf32(v.x); v.y = rna_tf32(v.y);
    v.z = rna_tf32(v.z); v.w = rna_tf32(v.w);
    *(float4*)(out + i) = v;
}

// ---------------------------------------------------------------------------
// TF32 mma.sync GEMM: C[M,N] = A[M,K] @ Bt[N,K]^T (+bias)(+res)(relu)(rnd)
// 128x128 CTA, BK=32, 256 threads (8 warps, 4x2 grid, 32x64 warp tile),
// 3-stage cp.async pipeline, swizzled ldmatrix fragments.
// A and Bt entries must already be tf32-rounded values.
// ---------------------------------------------------------------------------
#define GEMM_SMEM (3 * 32768)      // 3 stages x (A 16K + B 16K)

__device__ __forceinline__ void g_load_tile(const float* __restrict__ A,
                                            const float* __restrict__ Bt,
                                            int K, int m0, int n0, int kt,
                                            uint32_t aBase, uint32_t bBase,
                                            int tid) {
#pragma unroll
    for (int l = 0; l < 4; l++) {
        int idx = tid + (l << 8);            // 0..1023
        int r = idx >> 3;                    // row 0..127
        int c = idx & 7;                     // 16B chunk 0..7
        uint32_t dst = (uint32_t)((r << 7) + ((c ^ (r & 7)) << 4));
        CP16(aBase + dst, A + (size_t)(m0 + r) * K + kt + (c << 2));
        CP16(bBase + dst, Bt + (size_t)(n0 + r) * K + kt + (c << 2));
    }
}

__global__ __launch_bounds__(256, 2) void tc_gemm_kernel(
    const float* __restrict__ A, const float* __restrict__ Bt,
    const float* __restrict__ bias, const float* __restrict__ res,
    float* __restrict__ C, int M, int N, int K, int relu, int rnd)
{
    extern __shared__ __align__(1024) char smem[];
    const uint32_t sb = smem_u32(smem);
    const int tid = threadIdx.x;
    const int lid = tid & 31;
    const int wid = tid >> 5;
    const int wm = wid >> 1;           // 0..3  (32-row slice)
    const int wn = wid & 1;            // 0..1  (64-col slice)
    const int q  = lid >> 3;           // quad 0..3
    const int l7 = lid & 7;
    const int m0 = blockIdx.y * 128;
    const int n0 = blockIdx.x * 128;

    float acc[2][8][4];
#pragma unroll
    for (int i = 0; i < 2; i++)
#pragma unroll
        for (int j = 0; j < 8; j++)
#pragma unroll
            for (int k = 0; k < 4; k++) acc[i][j][k] = 0.f;

    const int NK = K >> 5;

    // prologue: stages 0, 1
    g_load_tile(A, Bt, K, m0, n0, 0, sb, sb + 16384, tid);
    CP_COMMIT();
    {
        uint32_t st = sb + 32768u;
        g_load_tile(A, Bt, K, m0, n0, 32, st, st + 16384, tid);
        CP_COMMIT();
    }

    for (int ks = 0; ks < NK; ks++) {
        if (ks + 1 < NK) CP_WAIT1(); else CP_WAIT0();
        __syncthreads();

        // issue load for stage ks+2 (overwrites stage ks-1's buffer; all
        // threads passed the barrier above after finishing compute ks-1)
        if (ks + 2 < NK) {
            uint32_t st = sb + (uint32_t)((ks + 2) % 3) * 32768u;
            g_load_tile(A, Bt, K, m0, n0, (ks + 2) << 5, st, st + 16384, tid);
            CP_COMMIT();
        }

        const uint32_t aB = sb + (uint32_t)(ks % 3) * 32768u;
        const uint32_t bB = aB + 16384u;

#pragma unroll
        for (int kk = 0; kk < 4; kk++) {          // k8-substeps
            uint32_t a[2][4], b[4][4];
#pragma unroll
            for (int mt = 0; mt < 2; mt++) {
                int row = wm * 32 + mt * 16 + (q & 1) * 8 + l7;
                int ch = kk * 2 + (q >> 1);
                uint32_t addr = aB + (uint32_t)((row << 7) + ((ch ^ (row & 7)) << 4));
                LDMX4(a[mt][0], a[mt][1], a[mt][2], a[mt][3], addr);
            }
#pragma unroll
            for (int np = 0; np < 4; np++) {
                int row = wn * 64 + np * 16 + (q >> 1) * 8 + l7;
                int ch = kk * 2 + (q & 1);
                uint32_t addr = bB + (uint32_t)((row << 7) + ((ch ^ (row & 7)) << 4));
                LDMX4(b[np][0], b[np][1], b[np][2], b[np][3], addr);
            }
#pragma unroll
            for (int mt = 0; mt < 2; mt++)
#pragma unroll
                for (int nt = 0; nt < 8; nt++)
                    MMA_TF32(acc[mt][nt], a[mt],
                             b[nt >> 1][(nt & 1) * 2],
                             b[nt >> 1][(nt & 1) * 2 + 1]);
        }
        __syncthreads();
    }

    // epilogue
    const int gid = lid >> 2;          // 0..7
    const int tig = lid & 3;           // 0..3
#pragma unroll
    for (int mt = 0; mt < 2; mt++) {
        int r0 = m0 + wm * 32 + mt * 16 + gid;
        int r1 = r0 + 8;
        float* c0row = C + (size_t)r0 * N;
        float* c1row = C + (size_t)r1 * N;
        const float* res0 = res ? res + (size_t)r0 * N : nullptr;
        const float* res1 = res ? res + (size_t)r1 * N : nullptr;
#pragma unroll
        for (int nt = 0; nt < 8; nt++) {
            int col = n0 + wn * 64 + nt * 8 + tig * 2;
            float2 v0 = make_float2(acc[mt][nt][0], acc[mt][nt][1]);
            float2 v1 = make_float2(acc[mt][nt][2], acc[mt][nt][3]);
            if (bias) {
                float2 bb = *(const float2*)(bias + col);
                v0.x += bb.x; v0.y += bb.y;
                v1.x += bb.x; v1.y += bb.y;
            }
            if (res) {
                float2 ra = *(const float2*)(res0 + col);
                float2 rb = *(const float2*)(res1 + col);
                v0.x += ra.x; v0.y += ra.y;
                v1.x += rb.x; v1.y += rb.y;
            }
            if (relu) {
                v0.x = fmaxf(v0.x, 0.f); v0.y = fmaxf(v0.y, 0.f);
                v1.x = fmaxf(v1.x, 0.f); v1.y = fmaxf(v1.y, 0.f);
            }
            if (rnd) {
                v0.x = rna_tf32(v0.x); v0.y = rna_tf32(v0.y);
                v1.x = rna_tf32(v1.x); v1.y = rna_tf32(v1.y);
            }
            *(float2*)(c0row + col) = v0;
            *(float2*)(c1row + col) = v1;
        }
    }
}

// ---------------------------------------------------------------------------
// Flash attention (causal), fp32. One block = 128 query rows for one (b,h).
// Output rounded to tf32 (feeds the projection GEMM).
// ---------------------------------------------------------------------------
#define QT_S 132
#define KT_S 68
#define PT_S 132
#define FLASH_SMEM ((64*QT_S + 64*KT_S + 64*64 + 64*PT_S) * 4)

__global__ __launch_bounds__(256) void flash_kernel(
    const float* __restrict__ qkv, float* __restrict__ out)
{
    extern __shared__ float smf[];
    float* Qt = smf;
    float* Kt = Qt + 64 * QT_S;
    float* Vs = Kt + 64 * KT_S;
    float* Pt = Vs + 64 * 64;

    const int tid = threadIdx.x;
    const int tx = tid & 15;
    const int ty = tid >> 4;
    const int q0 = blockIdx.x * 128;
    const int h = blockIdx.y;
    const int b = blockIdx.z;
    const float scale = 0.125f;
    const size_t rs = 3 * CC;

    const float* qbase = qkv + ((size_t)b * CT + q0) * rs + h * 64;
    const float* kbase = qkv + (size_t)b * CT * rs + CC + h * 64;
    const float* vbase = kbase + CC;

#pragma unroll
    for (int l = 0; l < 8; l++) {
        int idx = tid + l * 256;
        int r = idx >> 4;
        int d4 = (idx & 15) * 4;
        float4 qv = *(const float4*)(qbase + (size_t)r * rs + d4);
        Qt[(d4 + 0) * QT_S + r] = qv.x;
        Qt[(d4 + 1) * QT_S + r] = qv.y;
        Qt[(d4 + 2) * QT_S + r] = qv.z;
        Qt[(d4 + 3) * QT_S + r] = qv.w;
    }

    float m[8], lsum[8];
    float o[8][4];
#pragma unroll
    for (int i = 0; i < 8; i++) {
        m[i] = -1e30f; lsum[i] = 0.f;
#pragma unroll
        for (int c = 0; c < 4; c++) o[i][c] = 0.f;
    }

    const int jmax = (q0 + 127) >> 6;
    for (int j = 0; j <= jmax; j++) {
        __syncthreads();
        const float* kp = kbase + (size_t)(j * 64) * rs;
        const float* vp = vbase + (size_t)(j * 64) * rs;
#pragma unroll
        for (int l = 0; l < 4; l++) {
            int idx = tid + l * 256;
            int r = idx >> 4;
            int d4 = (idx & 15) * 4;
            float4 kv = *(const float4*)(kp + (size_t)r * rs + d4);
            Kt[(d4 + 0) * KT_S + r] = kv.x;
            Kt[(d4 + 1) * KT_S + r] = kv.y;
            Kt[(d4 + 2) * KT_S + r] = kv.z;
            Kt[(d4 + 3) * KT_S + r] = kv.w;
            float4 vv = *(const float4*)(vp + (size_t)r * rs + d4);
            *(float4*)&Vs[r * 64 + d4] = vv;
        }
        __syncthreads();

        float s[8][4];
#pragma unroll
        for (int i = 0; i < 8; i++)
#pragma unroll
            for (int c = 0; c < 4; c++) s[i][c] = 0.f;

#pragma unroll 8
        for (int d = 0; d < 64; d++) {
            float4 kv = *(float4*)&Kt[d * KT_S + tx * 4];
            float4 qa = *(float4*)&Qt[d * QT_S + ty * 8];
            float4 qb = *(float4*)&Qt[d * QT_S + ty * 8 + 4];
            float qv[8] = {qa.x, qa.y, qa.z, qa.w, qb.x, qb.y, qb.z, qb.w};
            float kk[4] = {kv.x, kv.y, kv.z, kv.w};
#pragma unroll
            for (int i = 0; i < 8; i++)
#pragma unroll
                for (int c = 0; c < 4; c++)
                    s[i][c] += qv[i] * kk[c];
        }

        const bool domask = (j * 64 + 63 > q0);
#pragma unroll
        for (int i = 0; i < 8; i++) {
            int qrow = q0 + ty * 8 + i;
            float sv[4];
#pragma unroll
            for (int c = 0; c < 4; c++) {
                float v = s[i][c] * scale;
                if (domask && (j * 64 + tx * 4 + c > qrow)) v = -1e30f;
                sv[c] = v;
            }
            float mloc = fmaxf(fmaxf(sv[0], sv[1]), fmaxf(sv[2], sv[3]));
#pragma unroll
            for (int off = 8; off >= 1; off >>= 1)
                mloc = fmaxf(mloc, __shfl_xor_sync(0xffffffffu, mloc, off, 16));
            float mnew = fmaxf(m[i], mloc);
            float corr = __expf(m[i] - mnew);
            float p[4];
            float ls = 0.f;
#pragma unroll
            for (int c = 0; c < 4; c++) {
                p[c] = __expf(sv[c] - mnew);
                ls += p[c];
            }
#pragma unroll
            for (int off = 8; off >= 1; off >>= 1)
                ls += __shfl_xor_sync(0xffffffffu, ls, off, 16);
            lsum[i] = lsum[i] * corr + ls;
            m[i] = mnew;
#pragma unroll
            for (int c = 0; c < 4; c++) o[i][c] *= corr;
            int rr = ty * 8 + i;
#pragma unroll
            for (int c = 0; c < 4; c++)
                Pt[(tx * 4 + c) * PT_S + rr] = p[c];
        }
        __syncthreads();

#pragma unroll 8
        for (int c = 0; c < 64; c++) {
            float4 vv = *(float4*)&Vs[c * 64 + tx * 4];
            float4 pa = *(float4*)&Pt[c * PT_S + ty * 8];
            float4 pb = *(float4*)&Pt[c * PT_S + ty * 8 + 4];
            float pv[8] = {pa.x, pa.y, pa.z, pa.w, pb.x, pb.y, pb.z, pb.w};
#pragma unroll
            for (int i = 0; i < 8; i++) {
                o[i][0] += pv[i] * vv.x;
                o[i][1] += pv[i] * vv.y;
                o[i][2] += pv[i] * vv.z;
                o[i][3] += pv[i] * vv.w;
            }
        }
    }

    float* ob = out + ((size_t)b * CT + q0) * CC + h * 64;
#pragma unroll
    for (int i = 0; i < 8; i++) {
        float inv = 1.0f / lsum[i];
        float4 v;
        v.x = rna_tf32(o[i][0] * inv);
        v.y = rna_tf32(o[i][1] * inv);
        v.z = rna_tf32(o[i][2] * inv);
        v.w = rna_tf32(o[i][3] * inv);
        *(float4*)(ob + (size_t)(ty * 8 + i) * CC + tx * 4) = v;
    }
}

// ---------------------------------------------------------------------------
// LayerNorm over last dim (C=1024). rnd=1 rounds output to tf32.
// ---------------------------------------------------------------------------
__global__ __launch_bounds__(256) void ln_kernel(
    const float* __restrict__ in, const float* __restrict__ g,
    const float* __restrict__ bb, float* __restrict__ out, int rnd)
{
    const int row = blockIdx.x;
    const int tid = threadIdx.x;
    float4 v = *(const float4*)(in + (size_t)row * CC + tid * 4);
    float s = v.x + v.y + v.z + v.w;
    float q = v.x * v.x + v.y * v.y + v.z * v.z + v.w * v.w;
#pragma unroll
    for (int off = 16; off >= 1; off >>= 1) {
        s += __shfl_xor_sync(0xffffffffu, s, off);
        q += __shfl_xor_sync(0xffffffffu, q, off);
    }
    __shared__ float ss[8], sq[8];
    __shared__ float smu, srs;
    int w = tid >> 5;
    if ((tid & 31) == 0) { ss[w] = s; sq[w] = q; }
    __syncthreads();
    if (tid == 0) {
        float S = 0.f, Q = 0.f;
#pragma unroll
        for (int i = 0; i < 8; i++) { S += ss[i]; Q += sq[i]; }
        float mu = S * (1.0f / CC);
        float var = Q * (1.0f / CC) - mu * mu;
        smu = mu;
        srs = rsqrtf(var + 1e-5f);
    }
    __syncthreads();
    float mu = smu, r = srs;
    float4 gv = *(const float4*)(g + tid * 4);
    float4 bv = *(const float4*)(bb + tid * 4);
    float4 ov;
    ov.x = (v.x - mu) * r * gv.x + bv.x;
    ov.y = (v.y - mu) * r * gv.y + bv.y;
    ov.z = (v.z - mu) * r * gv.z + bv.z;
    ov.w = (v.w - mu) * r * gv.w + bv.w;
    if (rnd) {
        ov.x = rna_tf32(ov.x); ov.y = rna_tf32(ov.y);
        ov.z = rna_tf32(ov.z); ov.w = rna_tf32(ov.w);
    }
    *(float4*)(out + (size_t)row * CC + tid * 4) = ov;
}

// ---------------------------------------------------------------------------
// Launch
// ---------------------------------------------------------------------------
extern "C" void kernel_launch(void* const* d_in, const int* in_sizes, int n_in,
                              void* d_out, int out_size)
{
    const float* x   = (const float*)d_in[0];
    const float* Wq  = (const float*)d_in[1];
    const float* Wk  = (const float*)d_in[2];
    const float* Wv  = (const float*)d_in[3];
    const float* Wp  = (const float*)d_in[4];
    const float* bp  = (const float*)d_in[5];
    const float* W1  = (const float*)d_in[6];
    const float* b1  = (const float*)d_in[7];
    const float* W2  = (const float*)d_in[8];
    const float* b2  = (const float*)d_in[9];
    const float* g1  = (const float*)d_in[10];
    const float* be1 = (const float*)d_in[11];
    const float* g2  = (const float*)d_in[12];
    const float* be2 = (const float*)d_in[13];

    float *WqkvT, *WpT, *W1T, *W2T, *xr, *qkvp, *attn, *x1, *xln1, *ffn, *x2;
    cudaGetSymbolAddress((void**)&WqkvT, g_WqkvT);
    cudaGetSymbolAddress((void**)&WpT,   g_WpT);
    cudaGetSymbolAddress((void**)&W1T,   g_W1T);
    cudaGetSymbolAddress((void**)&W2T,   g_W2T);
    cudaGetSymbolAddress((void**)&xr,    g_xr);
    cudaGetSymbolAddress((void**)&qkvp,  g_qkv);
    cudaGetSymbolAddress((void**)&attn,  g_attn);
    cudaGetSymbolAddress((void**)&x1,    g_x1);
    cudaGetSymbolAddress((void**)&xln1,  g_xln1);
    cudaGetSymbolAddress((void**)&ffn,   g_ffn);
    cudaGetSymbolAddress((void**)&x2,    g_x2);

    cudaFuncSetAttribute(flash_kernel,
                         cudaFuncAttributeMaxDynamicSharedMemorySize, FLASH_SMEM);
    cudaFuncSetAttribute(tc_gemm_kernel,
                         cudaFuncAttributeMaxDynamicSharedMemorySize, GEMM_SMEM);

    // 1) weight prep (tf32-rounded): repack+transpose QKV; transpose Wp/W1/W2
    repackT_kernel<<<3 * CC * CC / 256, 256>>>(Wq, Wk, Wv, WqkvT);
    transpose_kernel<<<dim3(CC / 32, CC / 32), dim3(32, 8)>>>(Wp, WpT, CC, CC);
    transpose_kernel<<<dim3(4 * CC / 32, CC / 32), dim3(32, 8)>>>(W1, W1T, CC, 4 * CC);
    transpose_kernel<<<dim3(CC / 32, 4 * CC / 32), dim3(32, 8)>>>(W2, W2T, 4 * CC, CC);
    round_copy_kernel<<<MROWS * CC / 1024, 256>>>(x, xr);

    // 2) QKV = Xr @ Wqkv  [4096, 3072]
    tc_gemm_kernel<<<dim3(3 * CC / 128, MROWS / 128), 256, GEMM_SMEM>>>(
        xr, WqkvT, nullptr, nullptr, qkvp, MROWS, 3 * CC, CC, 0, 0);

    // 3) flash attention -> attn [4096, 1024] (tf32-rounded output)
    flash_kernel<<<dim3(CT / 128, CH, CB), 256, FLASH_SMEM>>>(qkvp, attn);

    // 4) x1 = attn @ Wp + bp + x
    tc_gemm_kernel<<<dim3(CC / 128, MROWS / 128), 256, GEMM_SMEM>>>(
        attn, WpT, bp, x, x1, MROWS, CC, CC, 0, 0);

    // 5) xln1 = LN(x1), rounded (feeds FFN1 and residual)
    ln_kernel<<<MROWS, 256>>>(x1, g1, be1, xln1, 1);

    // 6) ffn = relu(xln1 @ W1 + b1), rounded (feeds FFN2)
    tc_gemm_kernel<<<dim3(4 * CC / 128, MROWS / 128), 256, GEMM_SMEM>>>(
        xln1, W1T, b1, nullptr, ffn, MROWS, 4 * CC, CC, 1, 1);

    // 7) x2 = ffn @ W2 + b2 + xln1
    tc_gemm_kernel<<<dim3(CC / 128, MROWS / 128), 256, GEMM_SMEM>>>(
        ffn, W2T, b2, xln1, x2, MROWS, CC, 4 * CC, 0, 0);

    // 8) out = LN(x2), unrounded
    ln_kernel<<<MROWS, 256>>>(x2, g2, be2, (float*)d_out, 0);
}

// round 6
// speedup vs baseline: 2.6978x; 1.2151x over previous
#include <cuda_runtime.h>
#include <cuda_fp16.h>
#include <cstdint>
#include <cstddef>

// Problem constants
#define CB 2
#define CT 2048
#define CC 1024
#define CH 16
#define CHD 64
#define MROWS (CB*CT)          // 4096

// ---------------------------------------------------------------------------
// Helpers
// ---------------------------------------------------------------------------
__device__ __forceinline__ uint32_t smem_u32(const void* p) {
    uint32_t a;
    asm("{ .reg .u64 t; cvta.to.shared.u64 t, %1; cvt.u32.u64 %0, t; }"
        : "=r"(a) : "l"(p));
    return a;
}

#define CP16(dst, src) \
    asm volatile("cp.async.cg.shared.global [%0], [%1], 16;" \
        :: "r"((uint32_t)(dst)), "l"(__cvta_generic_to_global((const void*)(src))))
#define CP_COMMIT() asm volatile("cp.async.commit_group;")
#define CP_WAIT1()  asm volatile("cp.async.wait_group 1;" ::: "memory")
#define CP_WAIT0()  asm volatile("cp.async.wait_group 0;" ::: "memory")

#define LDMX4(r0, r1, r2, r3, addr) \
    asm volatile("ldmatrix.sync.aligned.m8n8.x4.shared.b16 {%0,%1,%2,%3}, [%4];" \
        : "=r"(r0), "=r"(r1), "=r"(r2), "=r"(r3) : "r"(addr))

#define MMA_F16(c, a, b0_, b1_) \
    asm volatile("mma.sync.aligned.m16n8k16.row.col.f32.f16.f16.f32 " \
        "{%0,%1,%2,%3}, {%4,%5,%6,%7}, {%8,%9}, {%0,%1,%2,%3};" \
        : "+f"((c)[0]), "+f"((c)[1]), "+f"((c)[2]), "+f"((c)[3]) \
        : "r"((a)[0]), "r"((a)[1]), "r"((a)[2]), "r"((a)[3]), \
          "r"(b0_), "r"(b1_))

// ---------------------------------------------------------------------------
// Scratch (device globals — no allocation allowed)
// ---------------------------------------------------------------------------
__device__ __half g_WqkvTh[(size_t)3 * CC * CC];        // [3072, 1024]
__device__ __half g_WpTh  [(size_t)CC * CC];
__device__ __half g_W1Th  [(size_t)4 * CC * CC];
__device__ __half g_W2Th  [(size_t)CC * 4 * CC];
__device__ __half g_xh    [(size_t)MROWS * CC];         // x as fp16 (GEMM A)
__device__ float  g_qkv   [(size_t)MROWS * 3 * CC];     // fp32 (flash input)
__device__ __half g_attnh [(size_t)MROWS * CC];
__device__ float  g_x1    [(size_t)MROWS * CC];
__device__ float  g_xln1  [(size_t)MROWS * CC];         // fp32 (residual)
__device__ __half g_xln1h [(size_t)MROWS * CC];         // fp16 (GEMM A)
__device__ __half g_ffnh  [(size_t)MROWS * 4 * CC];
__device__ float  g_x2    [(size_t)MROWS * CC];

// ---------------------------------------------------------------------------
// repack+transpose QKV weights: [H, C, HD] x3 -> [3C, C] fp16
// ---------------------------------------------------------------------------
__global__ void repackT_kernel(const float* __restrict__ Wq,
                               const float* __restrict__ Wk,
                               const float* __restrict__ Wv,
                               __half* __restrict__ Wt) {
    int idx = blockIdx.x * 256 + threadIdx.x;   // over 3C*C
    int c = idx & 1023;
    int n = idx >> 10;
    int sel = n >> 10;
    int hn = n & 1023;
    int h = hn >> 6;
    int d = hn & 63;
    const float* W = (sel == 0) ? Wq : (sel == 1) ? Wk : Wv;
    Wt[(size_t)n * CC + c] = __float2half_rn(W[((size_t)h * CC + c) * CHD + d]);
}

// ---------------------------------------------------------------------------
// Tiled transpose to fp16: in [K, N] fp32 -> out [N, K] fp16
// ---------------------------------------------------------------------------
__global__ void transpose_kernel(const float* __restrict__ in,
                                 __half* __restrict__ out, int K, int N) {
    __shared__ float t[32][33];
    int n0 = blockIdx.x * 32;
    int k0 = blockIdx.y * 32;
    int x = threadIdx.x, y = threadIdx.y;     // 32 x 8
#pragma unroll
    for (int i = 0; i < 32; i += 8)
        t[y + i][x] = in[(size_t)(k0 + y + i) * N + n0 + x];
    __syncthreads();
#pragma unroll
    for (int i = 0; i < 32; i += 8)
        out[(size_t)(n0 + y + i) * K + k0 + x] = __float2half_rn(t[x][y + i]);
}

// ---------------------------------------------------------------------------
// Elementwise fp32 -> fp16 copy
// ---------------------------------------------------------------------------
__global__ void half_copy_kernel(const float* __restrict__ in,
                                 __half* __restrict__ out) {
    size_t i = ((size_t)blockIdx.x * 256 + threadIdx.x) * 4;
    float4 v = *(const float4*)(in + i);
    __half2 h0 = __floats2half2_rn(v.x, v.y);
    __half2 h1 = __floats2half2_rn(v.z, v.w);
    *(__half2*)(out + i) = h0;
    *(__half2*)(out + i + 2) = h1;
}

// ---------------------------------------------------------------------------
// FP16 mma.sync GEMM: C[M,N] = A[M,K] @ Bt[N,K]^T (+bias)(+res)(relu)
// 128x128 CTA, BK=64 (halves), 256 threads (8 warps 4x2, 32x64 warp tile),
// 3-stage cp.async pipeline. Output: fp32 C (if non-null) and/or fp16 Ch.
// ---------------------------------------------------------------------------
#define GEMM_SMEM (3 * 32768)      // 3 stages x (A 16K + B 16K)

__device__ __forceinline__ void g_load_tile(const __half* __restrict__ A,
                                            const __half* __restrict__ Bt,
                                            int K, int m0, int n0, int kt,
                                            uint32_t aBase, uint32_t bBase,
                                            int tid) {
#pragma unroll
    for (int l = 0; l < 4; l++) {
        int idx = tid + (l << 8);            // 0..1023
        int r = idx >> 3;                    // row 0..127
        int c = idx & 7;                     // 16B chunk (8 halves) 0..7
        uint32_t dst = (uint32_t)((r << 7) + ((c ^ (r & 7)) << 4));
        CP16(aBase + dst, A + (size_t)(m0 + r) * K + kt + (c << 3));
        CP16(bBase + dst, Bt + (size_t)(n0 + r) * K + kt + (c << 3));
    }
}

__global__ __launch_bounds__(256, 2) void tc_gemm_kernel(
    const __half* __restrict__ A, const __half* __restrict__ Bt,
    const float* __restrict__ bias, const float* __restrict__ res,
    float* __restrict__ C, __half* __restrict__ Ch,
    int M, int N, int K, int relu)
{
    extern __shared__ __align__(1024) char smem[];
    const uint32_t sb = smem_u32(smem);
    const int tid = threadIdx.x;
    const int lid = tid & 31;
    const int wid = tid >> 5;
    const int wm = wid >> 1;           // 0..3  (32-row slice)
    const int wn = wid & 1;            // 0..1  (64-col slice)
    const int q  = lid >> 3;           // quad 0..3
    const int l7 = lid & 7;
    const int m0 = blockIdx.y * 128;
    const int n0 = blockIdx.x * 128;

    float acc[2][8][4];
#pragma unroll
    for (int i = 0; i < 2; i++)
#pragma unroll
        for (int j = 0; j < 8; j++)
#pragma unroll
            for (int k = 0; k < 4; k++) acc[i][j][k] = 0.f;

    const int NK = K >> 6;

    // prologue: stages 0, 1
    g_load_tile(A, Bt, K, m0, n0, 0, sb, sb + 16384, tid);
    CP_COMMIT();
    {
        uint32_t st = sb + 32768u;
        g_load_tile(A, Bt, K, m0, n0, 64, st, st + 16384, tid);
        CP_COMMIT();
    }

    for (int ks = 0; ks < NK; ks++) {
        if (ks + 1 < NK) CP_WAIT1(); else CP_WAIT0();
        __syncthreads();

        if (ks + 2 < NK) {
            uint32_t st = sb + (uint32_t)((ks + 2) % 3) * 32768u;
            g_load_tile(A, Bt, K, m0, n0, (ks + 2) << 6, st, st + 16384, tid);
            CP_COMMIT();
        }

        const uint32_t aB = sb + (uint32_t)(ks % 3) * 32768u;
        const uint32_t bB = aB + 16384u;

#pragma unroll
        for (int kk = 0; kk < 4; kk++) {          // k16-substeps
            uint32_t a[2][4], b[4][4];
#pragma unroll
            for (int mt = 0; mt < 2; mt++) {
                int row = wm * 32 + mt * 16 + (q & 1) * 8 + l7;
                int ch = kk * 2 + (q >> 1);
                uint32_t addr = aB + (uint32_t)((row << 7) + ((ch ^ (row & 7)) << 4));
                LDMX4(a[mt][0], a[mt][1], a[mt][2], a[mt][3], addr);
            }
#pragma unroll
            for (int np = 0; np < 4; np++) {
                int row = wn * 64 + np * 16 + (q & 1) * 8 + l7;
                int ch = kk * 2 + (q >> 1);
                uint32_t addr = bB + (uint32_t)((row << 7) + ((ch ^ (row & 7)) << 4));
                LDMX4(b[np][0], b[np][1], b[np][2], b[np][3], addr);
            }
            // n-tile (np, lower 8): {b[np][0], b[np][2]}; upper: {b[np][1], b[np][3]}
#pragma unroll
            for (int mt = 0; mt < 2; mt++)
#pragma unroll
                for (int nt = 0; nt < 8; nt++)
                    MMA_F16(acc[mt][nt], a[mt],
                            b[nt >> 1][nt & 1],
                            b[nt >> 1][(nt & 1) + 2]);
        }
        __syncthreads();
    }

    // epilogue
    const int gid = lid >> 2;          // 0..7
    const int tig = lid & 3;           // 0..3
#pragma unroll
    for (int mt = 0; mt < 2; mt++) {
        int r0 = m0 + wm * 32 + mt * 16 + gid;
        int r1 = r0 + 8;
        const float* res0 = res ? res + (size_t)r0 * N : nullptr;
        const float* res1 = res ? res + (size_t)r1 * N : nullptr;
#pragma unroll
        for (int nt = 0; nt < 8; nt++) {
            int col = n0 + wn * 64 + nt * 8 + tig * 2;
            float2 v0 = make_float2(acc[mt][nt][0], acc[mt][nt][1]);
            float2 v1 = make_float2(acc[mt][nt][2], acc[mt][nt][3]);
            if (bias) {
                float2 bb = *(const float2*)(bias + col);
                v0.x += bb.x; v0.y += bb.y;
                v1.x += bb.x; v1.y += bb.y;
            }
            if (res) {
                float2 ra = *(const float2*)(res0 + col);
                float2 rb = *(const float2*)(res1 + col);
                v0.x += ra.x; v0.y += ra.y;
                v1.x += rb.x; v1.y += rb.y;
            }
            if (relu) {
                v0.x = fmaxf(v0.x, 0.f); v0.y = fmaxf(v0.y, 0.f);
                v1.x = fmaxf(v1.x, 0.f); v1.y = fmaxf(v1.y, 0.f);
            }
            if (C) {
                *(float2*)(C + (size_t)r0 * N + col) = v0;
                *(float2*)(C + (size_t)r1 * N + col) = v1;
            }
            if (Ch) {
                *(__half2*)(Ch + (size_t)r0 * N + col) = __floats2half2_rn(v0.x, v0.y);
                *(__half2*)(Ch + (size_t)r1 * N + col) = __floats2half2_rn(v1.x, v1.y);
            }
        }
    }
}

// ---------------------------------------------------------------------------
// Flash attention (causal), fp32 compute. One block = 128 query rows, one (b,h).
// qkv layout: [B*T, 3072] fp32; output fp16 [B*T, 1024] concat-heads.
// ---------------------------------------------------------------------------
#define QT_S 132
#define KT_S 68
#define PT_S 132
#define FLASH_SMEM ((64*QT_S + 64*KT_S + 64*64 + 64*PT_S) * 4)

__global__ __launch_bounds__(256) void flash_kernel(
    const float* __restrict__ qkv, __half* __restrict__ out)
{
    extern __shared__ float smf[];
    float* Qt = smf;
    float* Kt = Qt + 64 * QT_S;
    float* Vs = Kt + 64 * KT_S;
    float* Pt = Vs + 64 * 64;

    const int tid = threadIdx.x;
    const int tx = tid & 15;
    const int ty = tid >> 4;
    const int q0 = blockIdx.x * 128;
    const int h = blockIdx.y;
    const int b = blockIdx.z;
    const float scale = 0.125f;
    const size_t rs = 3 * CC;

    const float* qbase = qkv + ((size_t)b * CT + q0) * rs + h * 64;
    const float* kbase = qkv + (size_t)b * CT * rs + CC + h * 64;
    const float* vbase = kbase + CC;

#pragma unroll
    for (int l = 0; l < 8; l++) {
        int idx = tid + l * 256;
        int r = idx >> 4;
        int d4 = (idx & 15) * 4;
        float4 qv = *(const float4*)(qbase + (size_t)r * rs + d4);
        Qt[(d4 + 0) * QT_S + r] = qv.x;
        Qt[(d4 + 1) * QT_S + r] = qv.y;
        Qt[(d4 + 2) * QT_S + r] = qv.z;
        Qt[(d4 + 3) * QT_S + r] = qv.w;
    }

    float m[8], lsum[8];
    float o[8][4];
#pragma unroll
    for (int i = 0; i < 8; i++) {
        m[i] = -1e30f; lsum[i] = 0.f;
#pragma unroll
        for (int c = 0; c < 4; c++) o[i][c] = 0.f;
    }

    const int jmax = (q0 + 127) >> 6;
    for (int j = 0; j <= jmax; j++) {
        __syncthreads();
        const float* kp = kbase + (size_t)(j * 64) * rs;
        const float* vp = vbase + (size_t)(j * 64) * rs;
#pragma unroll
        for (int l = 0; l < 4; l++) {
            int idx = tid + l * 256;
            int r = idx >> 4;
            int d4 = (idx & 15) * 4;
            float4 kv = *(const float4*)(kp + (size_t)r * rs + d4);
            Kt[(d4 + 0) * KT_S + r] = kv.x;
            Kt[(d4 + 1) * KT_S + r] = kv.y;
            Kt[(d4 + 2) * KT_S + r] = kv.z;
            Kt[(d4 + 3) * KT_S + r] = kv.w;
            float4 vv = *(const float4*)(vp + (size_t)r * rs + d4);
            *(float4*)&Vs[r * 64 + d4] = vv;
        }
        __syncthreads();

        float s[8][4];
#pragma unroll
        for (int i = 0; i < 8; i++)
#pragma unroll
            for (int c = 0; c < 4; c++) s[i][c] = 0.f;

#pragma unroll 8
        for (int d = 0; d < 64; d++) {
            float4 kv = *(float4*)&Kt[d * KT_S + tx * 4];
            float4 qa = *(float4*)&Qt[d * QT_S + ty * 8];
            float4 qb = *(float4*)&Qt[d * QT_S + ty * 8 + 4];
            float qv[8] = {qa.x, qa.y, qa.z, qa.w, qb.x, qb.y, qb.z, qb.w};
            float kk[4] = {kv.x, kv.y, kv.z, kv.w};
#pragma unroll
            for (int i = 0; i < 8; i++)
#pragma unroll
                for (int c = 0; c < 4; c++)
                    s[i][c] += qv[i] * kk[c];
        }

        const bool domask = (j * 64 + 63 > q0);
#pragma unroll
        for (int i = 0; i < 8; i++) {
            int qrow = q0 + ty * 8 + i;
            float sv[4];
#pragma unroll
            for (int c = 0; c < 4; c++) {
                float v = s[i][c] * scale;
                if (domask && (j * 64 + tx * 4 + c > qrow)) v = -1e30f;
                sv[c] = v;
            }
            float mloc = fmaxf(fmaxf(sv[0], sv[1]), fmaxf(sv[2], sv[3]));
#pragma unroll
            for (int off = 8; off >= 1; off >>= 1)
                mloc = fmaxf(mloc, __shfl_xor_sync(0xffffffffu, mloc, off, 16));
            float mnew = fmaxf(m[i], mloc);
            float corr = __expf(m[i] - mnew);
            float p[4];
            float ls = 0.f;
#pragma unroll
            for (int c = 0; c < 4; c++) {
                p[c] = __expf(sv[c] - mnew);
                ls += p[c];
            }
#pragma unroll
            for (int off = 8; off >= 1; off >>= 1)
                ls += __shfl_xor_sync(0xffffffffu, ls, off, 16);
            lsum[i] = lsum[i] * corr + ls;
            m[i] = mnew;
#pragma unroll
            for (int c = 0; c < 4; c++) o[i][c] *= corr;
            int rr = ty * 8 + i;
#pragma unroll
            for (int c = 0; c < 4; c++)
                Pt[(tx * 4 + c) * PT_S + rr] = p[c];
        }
        __syncthreads();

#pragma unroll 8
        for (int c = 0; c < 64; c++) {
            float4 vv = *(float4*)&Vs[c * 64 + tx * 4];
            float4 pa = *(float4*)&Pt[c * PT_S + ty * 8];
            float4 pb = *(float4*)&Pt[c * PT_S + ty * 8 + 4];
            float pv[8] = {pa.x, pa.y, pa.z, pa.w, pb.x, pb.y, pb.z, pb.w};
#pragma unroll
            for (int i = 0; i < 8; i++) {
                o[i][0] += pv[i] * vv.x;
                o[i][1] += pv[i] * vv.y;
                o[i][2] += pv[i] * vv.z;
                o[i][3] += pv[i] * vv.w;
            }
        }
    }

    __half* ob = out + ((size_t)b * CT + q0) * CC + h * 64;
#pragma unroll
    for (int i = 0; i < 8; i++) {
        float inv = 1.0f / lsum[i];
        __half2 h0 = __floats2half2_rn(o[i][0] * inv, o[i][1] * inv);
        __half2 h1 = __floats2half2_rn(o[i][2] * inv, o[i][3] * inv);
        __half* p = ob + (size_t)(ty * 8 + i) * CC + tx * 4;
        *(__half2*)p = h0;
        *(__half2*)(p + 2) = h1;
    }
}

// ---------------------------------------------------------------------------
// LayerNorm over last dim (C=1024). Writes fp32 out; optional fp16 copy.
// ---------------------------------------------------------------------------
__global__ __launch_bounds__(256) void ln_kernel(
    const float* __restrict__ in, const float* __restrict__ g,
    const float* __restrict__ bb, float* __restrict__ out,
    __half* __restrict__ outh)
{
    const int row = blockIdx.x;
    const int tid = threadIdx.x;
    float4 v = *(const float4*)(in + (size_t)row * CC + tid * 4);
    float s = v.x + v.y + v.z + v.w;
    float q = v.x * v.x + v.y * v.y + v.z * v.z + v.w * v.w;
#pragma unroll
    for (int off = 16; off >= 1; off >>= 1) {
        s += __shfl_xor_sync(0xffffffffu, s, off);
        q += __shfl_xor_sync(0xffffffffu, q, off);
    }
    __shared__ float ss[8], sq[8];
    __shared__ float smu, srs;
    int w = tid >> 5;
    if ((tid & 31) == 0) { ss[w] = s; sq[w] = q; }
    __syncthreads();
    if (tid == 0) {
        float S = 0.f, Q = 0.f;
#pragma unroll
        for (int i = 0; i < 8; i++) { S += ss[i]; Q += sq[i]; }
        float mu = S * (1.0f / CC);
        float var = Q * (1.0f / CC) - mu * mu;
        smu = mu;
        srs = rsqrtf(var + 1e-5f);
    }
    __syncthreads();
    float mu = smu, r = srs;
    float4 gv = *(const float4*)(g + tid * 4);
    float4 bv = *(const float4*)(bb + tid * 4);
    float4 ov;
    ov.x = (v.x - mu) * r * gv.x + bv.x;
    ov.y = (v.y - mu) * r * gv.y + bv.y;
    ov.z = (v.z - mu) * r * gv.z + bv.z;
    ov.w = (v.w - mu) * r * gv.w + bv.w;
    *(float4*)(out + (size_t)row * CC + tid * 4) = ov;
    if (outh) {
        __half* p = outh + (size_t)row * CC + tid * 4;
        *(__half2*)p = __floats2half2_rn(ov.x, ov.y);
        *(__half2*)(p + 2) = __floats2half2_rn(ov.z, ov.w);
    }
}

// ---------------------------------------------------------------------------
// Launch
// ---------------------------------------------------------------------------
extern "C" void kernel_launch(void* const* d_in, const int* in_sizes, int n_in,
                              void* d_out, int out_size)
{
    const float* x   = (const float*)d_in[0];
    const float* Wq  = (const float*)d_in[1];
    const float* Wk  = (const float*)d_in[2];
    const float* Wv  = (const float*)d_in[3];
    const float* Wp  = (const float*)d_in[4];
    const float* bp  = (const float*)d_in[5];
    const float* W1  = (const float*)d_in[6];
    const float* b1  = (const float*)d_in[7];
    const float* W2  = (const float*)d_in[8];
    const float* b2  = (const float*)d_in[9];
    const float* g1  = (const float*)d_in[10];
    const float* be1 = (const float*)d_in[11];
    const float* g2  = (const float*)d_in[12];
    const float* be2 = (const float*)d_in[13];

    __half *WqkvTh, *WpTh, *W1Th, *W2Th, *xh, *attnh, *xln1h, *ffnh;
    float *qkvp, *x1, *xln1, *x2;
    cudaGetSymbolAddress((void**)&WqkvTh, g_WqkvTh);
    cudaGetSymbolAddress((void**)&WpTh,   g_WpTh);
    cudaGetSymbolAddress((void**)&W1Th,   g_W1Th);
    cudaGetSymbolAddress((void**)&W2Th,   g_W2Th);
    cudaGetSymbolAddress((void**)&xh,     g_xh);
    cudaGetSymbolAddress((void**)&qkvp,   g_qkv);
    cudaGetSymbolAddress((void**)&attnh,  g_attnh);
    cudaGetSymbolAddress((void**)&x1,     g_x1);
    cudaGetSymbolAddress((void**)&xln1,   g_xln1);
    cudaGetSymbolAddress((void**)&xln1h,  g_xln1h);
    cudaGetSymbolAddress((void**)&ffnh,   g_ffnh);
    cudaGetSymbolAddress((void**)&x2,     g_x2);

    cudaFuncSetAttribute(flash_kernel,
                         cudaFuncAttributeMaxDynamicSharedMemorySize, FLASH_SMEM);
    cudaFuncSetAttribute(tc_gemm_kernel,
                         cudaFuncAttributeMaxDynamicSharedMemorySize, GEMM_SMEM);

    // 1) weight prep (fp16): repack+transpose QKV; transpose Wp/W1/W2; x -> fp16
    repackT_kernel<<<3 * CC * CC / 256, 256>>>(Wq, Wk, Wv, WqkvTh);
    transpose_kernel<<<dim3(CC / 32, CC / 32), dim3(32, 8)>>>(Wp, WpTh, CC, CC);
    transpose_kernel<<<dim3(4 * CC / 32, CC / 32), dim3(32, 8)>>>(W1, W1Th, CC, 4 * CC);
    transpose_kernel<<<dim3(CC / 32, 4 * CC / 32), dim3(32, 8)>>>(W2, W2Th, 4 * CC, CC);
    half_copy_kernel<<<MROWS * CC / 1024, 256>>>(x, xh);

    // 2) QKV = Xh @ Wqkv  [4096, 3072] fp32 out
    tc_gemm_kernel<<<dim3(3 * CC / 128, MROWS / 128), 256, GEMM_SMEM>>>(
        xh, WqkvTh, nullptr, nullptr, qkvp, nullptr, MROWS, 3 * CC, CC, 0);

    // 3) flash attention -> attnh [4096, 1024] fp16
    flash_kernel<<<dim3(CT / 128, CH, CB), 256, FLASH_SMEM>>>(qkvp, attnh);

    // 4) x1 = attn @ Wp + bp + x   (fp32 out)
    tc_gemm_kernel<<<dim3(CC / 128, MROWS / 128), 256, GEMM_SMEM>>>(
        attnh, WpTh, bp, x, x1, nullptr, MROWS, CC, CC, 0);

    // 5) xln1 = LN(x1) -> fp32 (residual) + fp16 (GEMM A)
    ln_kernel<<<MROWS, 256>>>(x1, g1, be1, xln1, xln1h);

    // 6) ffnh = relu(xln1 @ W1 + b1)  fp16 out only
    tc_gemm_kernel<<<dim3(4 * CC / 128, MROWS / 128), 256, GEMM_SMEM>>>(
        xln1h, W1Th, b1, nullptr, nullptr, ffnh, MROWS, 4 * CC, CC, 1);

    // 7) x2 = ffn @ W2 + b2 + xln1   (fp32 out)
    tc_gemm_kernel<<<dim3(CC / 128, MROWS / 128), 256, GEMM_SMEM>>>(
        ffnh, W2Th, b2, xln1, x2, nullptr, MROWS, CC, 4 * CC, 0);

    // 8) out = LN(x2), fp32
    ln_kernel<<<MROWS, 256>>>(x2, g2, be2, (float*)d_out, nullptr);
}